// round 2
// baseline (speedup 1.0000x reference)
#include <cuda_runtime.h>
#include <math.h>

#define NT 49
#define CD 128
#define NH 4
#define DH 32

#define OS_LD 133
#define QS_LD 133
#define KT_LD 51
#define SS_LD 53
#define WS_LD 65

#define OS_SZ (NT*OS_LD)          /* x (stride 128) then O (stride 133) */
#define QS_SZ (NT*QS_LD)
#define KT_SZ (CD*KT_LD + 16)
#define VS_SZ (NT*CD)
#define SS_SZ (NT*SS_LD)          /* per head; 2 heads live at once */
#define WS_SZ (384*WS_LD)

#define SMEM_FLOATS (OS_SZ + QS_SZ + KT_SZ + VS_SZ + 2*SS_SZ + WS_SZ)
#define SMEM_BYTES (SMEM_FLOATS*4)

__device__ __forceinline__ float warp_max(float v) {
#pragma unroll
    for (int o = 16; o > 0; o >>= 1) v = fmaxf(v, __shfl_xor_sync(0xffffffffu, v, o));
    return v;
}
__device__ __forceinline__ float warp_sum(float v) {
#pragma unroll
    for (int o = 16; o > 0; o >>= 1) v += __shfl_xor_sync(0xffffffffu, v, o);
    return v;
}

__device__ __forceinline__ float rel_bias(const float* __restrict__ bt, int h, int i, int j) {
    int yi = i / 7, xi = i - yi * 7;
    int yj = j / 7, xj = j - yj * 7;
    int idx = (yi - yj + 6) * 13 + (xi - xj + 6);
    return bt[idx * NH + h];
}

__global__ __launch_bounds__(256, 1)
void win_attn_kernel(const float* __restrict__ x,
                     const float* __restrict__ mask,
                     const float* __restrict__ qkv_w,
                     const float* __restrict__ qkv_b,
                     const float* __restrict__ proj_w,
                     const float* __restrict__ proj_b,
                     const float* __restrict__ bt,
                     float* __restrict__ out,
                     int nW)
{
    extern __shared__ float sm[];
    float* osx = sm;                  // x [49][128] then O [49][133]
    float* qs  = osx + OS_SZ;         // Q [49][133]
    float* kts = qs + QS_SZ;          // K^T [128][51]
    float* vs  = kts + KT_SZ;         // V [49][128]
    float* ss  = vs + VS_SZ;          // S/P [2 heads][49][53]
    float* ws  = ss + 2 * SS_SZ;      // weight slab [384][65] (k-slab of 64)

    const int t = threadIdx.x;
    const int w = blockIdx.x;
    const long base = (long)w * (NT * CD);
    const int tn = t & 31, tm = t >> 5;

    // ---- load x ----
    for (int idx = t; idx < NT * CD; idx += 256) osx[idx] = x[base + idx];

    // ---- QKV GEMM: [49 x 384] = x[49x128] @ qkv_w^T ----
    {
        float acc[7][12];
#pragma unroll
        for (int r = 0; r < 7; r++)
#pragma unroll
            for (int c = 0; c < 12; c++) acc[r][c] = 0.f;

        const float4* w4 = reinterpret_cast<const float4*>(qkv_w);
        for (int ks = 0; ks < CD; ks += 64) {
            __syncthreads();
            // stage k-slab transposed-free: ws[col][kk], coalesced global reads
            for (int idx = t; idx < 384 * 16; idx += 256) {
                int col = idx >> 4, q = idx & 15;
                float4 v = w4[col * 32 + (ks >> 2) + q];
                float* p = &ws[col * WS_LD + q * 4];
                p[0] = v.x; p[1] = v.y; p[2] = v.z; p[3] = v.w;
            }
            __syncthreads();
            if (tm < 7) {
#pragma unroll 2
                for (int kk = 0; kk < 64; kk++) {
                    float a[7];
#pragma unroll
                    for (int r = 0; r < 7; r++) a[r] = osx[(tm * 7 + r) * CD + ks + kk];
#pragma unroll
                    for (int c = 0; c < 12; c++) {
                        float b = ws[(tn + 32 * c) * WS_LD + kk];
#pragma unroll
                        for (int r = 0; r < 7; r++) acc[r][c] = fmaf(a[r], b, acc[r][c]);
                    }
                }
            }
        }
        if (tm < 7) {
#pragma unroll
            for (int c = 0; c < 12; c++) {
                int col = tn + 32 * c;
                float bb = qkv_b[col];
#pragma unroll
                for (int r = 0; r < 7; r++) {
                    int row = tm * 7 + r;
                    float v = acc[r][c] + bb;
                    if (c < 4)       qs[row * QS_LD + col] = v;               // Q
                    else if (c < 8)  kts[(col - 128) * KT_LD + row] = v;      // K^T
                    else             vs[row * CD + (col - 256)] = v;          // V
                }
            }
        }
    }
    __syncthreads();

    // ---- attention, two heads at a time ----
    const float scale = 0.1767766952966369f; // 32^-0.5
    const float* mrow = mask + (long)(w % nW) * (NT * NT);

    for (int h0 = 0; h0 < NH; h0 += 2) {
        // S = Q K^T * scale
        {
            int th = t & 127, hh = t >> 7;
            if (th < 100) {
                int ip = th >> 2, jg = th & 3;
                int i0 = ip * 2;
                int h = h0 + hh;
                bool has1 = (i0 + 1) < NT;
                float accs0[13], accs1[13];
#pragma unroll
                for (int jj = 0; jj < 13; jj++) { accs0[jj] = 0.f; accs1[jj] = 0.f; }
                const float* qrow0 = &qs[i0 * QS_LD + h * DH];
                const float* qrow1 = &qs[(i0 + 1) * QS_LD + h * DH];
#pragma unroll 2
                for (int k = 0; k < DH; k++) {
                    float q0 = qrow0[k];
                    float q1 = has1 ? qrow1[k] : 0.f;
                    const float* krow = &kts[(h * DH + k) * KT_LD + jg * 13];
#pragma unroll
                    for (int jj = 0; jj < 13; jj++) {
                        float kv = krow[jj];
                        accs0[jj] = fmaf(q0, kv, accs0[jj]);
                        accs1[jj] = fmaf(q1, kv, accs1[jj]);
                    }
                }
                float* sp = ss + hh * SS_SZ;
#pragma unroll
                for (int jj = 0; jj < 13; jj++) {
                    int j = jg * 13 + jj;
                    if (j < NT) {
                        sp[i0 * SS_LD + j] = accs0[jj] * scale;
                        if (has1) sp[(i0 + 1) * SS_LD + j] = accs1[jj] * scale;
                    }
                }
            }
        }
        __syncthreads();

        // softmax rows (+ rel-pos bias + mask), warp per row
        {
            int wid = t >> 5, l = t & 31;
            int hh = wid >> 2, h = h0 + hh;
            float* sp = ss + hh * SS_SZ;
            for (int p = 0; p < 13; p++) {
                int i = (wid & 3) + 4 * p;
                if (i < NT) {
                    int j2 = l + 32;
                    bool has2 = j2 < NT;
                    float v0 = sp[i * SS_LD + l] + rel_bias(bt, h, i, l) + mrow[i * NT + l];
                    float v1 = has2 ? (sp[i * SS_LD + j2] + rel_bias(bt, h, i, j2) + mrow[i * NT + j2])
                                    : -1e30f;
                    float m = warp_max(fmaxf(v0, v1));
                    float e0 = __expf(v0 - m);
                    float e1 = has2 ? __expf(v1 - m) : 0.f;
                    float s = warp_sum(e0 + e1);
                    float inv = 1.f / s;
                    sp[i * SS_LD + l] = e0 * inv;
                    if (has2) sp[i * SS_LD + j2] = e1 * inv;
                }
            }
        }
        __syncthreads();

        // O = P V  (lanes over rows i, warp covers an 8-wide dh slice)
        {
            int g = t >> 5, l = t & 31;
            int hh = g >> 2, h = h0 + hh;
            int dh0 = (g & 3) * 8;
            const float* sp = ss + hh * SS_SZ;
            bool has2 = (l + 32) < NT;
            float acc0[8], acc1[8];
#pragma unroll
            for (int u = 0; u < 8; u++) { acc0[u] = 0.f; acc1[u] = 0.f; }
            for (int j = 0; j < NT; j++) {
                float p0 = sp[l * SS_LD + j];
                float p1 = has2 ? sp[(l + 32) * SS_LD + j] : 0.f;
                const float* vr = &vs[j * CD + h * DH + dh0];
#pragma unroll
                for (int u = 0; u < 8; u++) {
                    float vv = vr[u];
                    acc0[u] = fmaf(p0, vv, acc0[u]);
                    acc1[u] = fmaf(p1, vv, acc1[u]);
                }
            }
#pragma unroll
            for (int u = 0; u < 8; u++) {
                osx[l * OS_LD + h * DH + dh0 + u] = acc0[u];
                if (has2) osx[(l + 32) * OS_LD + h * DH + dh0 + u] = acc1[u];
            }
        }
        __syncthreads();
    }

    // ---- proj GEMM: out[49x128] = O[49x128] @ proj_w^T + b ----
    {
        float accp[7][4];
#pragma unroll
        for (int r = 0; r < 7; r++)
#pragma unroll
            for (int c = 0; c < 4; c++) accp[r][c] = 0.f;

        const float4* p4 = reinterpret_cast<const float4*>(proj_w);
        for (int ks = 0; ks < CD; ks += 64) {
            __syncthreads();
            for (int idx = t; idx < 128 * 16; idx += 256) {
                int col = idx >> 4, q = idx & 15;
                float4 v = p4[col * 32 + (ks >> 2) + q];
                float* p = &ws[col * WS_LD + q * 4];
                p[0] = v.x; p[1] = v.y; p[2] = v.z; p[3] = v.w;
            }
            __syncthreads();
            if (tm < 7) {
#pragma unroll 2
                for (int kk = 0; kk < 64; kk++) {
                    float a[7];
#pragma unroll
                    for (int r = 0; r < 7; r++) a[r] = osx[(tm * 7 + r) * OS_LD + ks + kk];
#pragma unroll
                    for (int c = 0; c < 4; c++) {
                        float b = ws[(tn + 32 * c) * WS_LD + kk];
#pragma unroll
                        for (int r = 0; r < 7; r++) accp[r][c] = fmaf(a[r], b, accp[r][c]);
                    }
                }
            }
        }
        if (tm < 7) {
#pragma unroll
            for (int c = 0; c < 4; c++) {
                int col = tn + 32 * c;
                float bb = proj_b[col];
#pragma unroll
                for (int r = 0; r < 7; r++) {
                    int row = tm * 7 + r;
                    out[base + row * CD + col] = accp[r][c] + bb;
                }
            }
        }
    }
}

extern "C" void kernel_launch(void* const* d_in, const int* in_sizes, int n_in,
                              void* d_out, int out_size) {
    const float* x      = (const float*)d_in[0];
    const float* mask   = (const float*)d_in[1];
    const float* qkv_w  = (const float*)d_in[2];
    const float* qkv_b  = (const float*)d_in[3];
    const float* proj_w = (const float*)d_in[4];
    const float* proj_b = (const float*)d_in[5];
    const float* bt     = (const float*)d_in[6];
    float* out = (float*)d_out;

    int B  = in_sizes[0] / (NT * CD);     // 16384
    int nW = in_sizes[1] / (NT * NT);     // 1024

    cudaFuncSetAttribute(win_attn_kernel,
                         cudaFuncAttributeMaxDynamicSharedMemorySize, SMEM_BYTES);
    win_attn_kernel<<<B, 256, SMEM_BYTES>>>(x, mask, qkv_w, qkv_b,
                                            proj_w, proj_b, bt, out, nW);
}

// round 3
// speedup vs baseline: 1.0000x; 1.0000x over previous
#include <cuda_runtime.h>
#include <math.h>

#define NT 49
#define CD 128
#define NH 4
#define DH 32

#define OS_LD 133
#define QS_LD 133
#define KT_LD 51
#define SS_LD 53
#define WS_LD 65

#define OS_SZ (NT*OS_LD)          /* x (stride 128) then O (stride 133) */
#define QS_SZ (NT*QS_LD)
#define KT_SZ (CD*KT_LD + 16)
#define VS_SZ (NT*CD)
#define SS_SZ (NT*SS_LD)          /* per head; 2 heads live at once */
#define WS_SZ (384*WS_LD)

#define SMEM_FLOATS (OS_SZ + QS_SZ + KT_SZ + VS_SZ + 2*SS_SZ + WS_SZ)
#define SMEM_BYTES (SMEM_FLOATS*4)

__device__ __forceinline__ float warp_max(float v) {
#pragma unroll
    for (int o = 16; o > 0; o >>= 1) v = fmaxf(v, __shfl_xor_sync(0xffffffffu, v, o));
    return v;
}
__device__ __forceinline__ float warp_sum(float v) {
#pragma unroll
    for (int o = 16; o > 0; o >>= 1) v += __shfl_xor_sync(0xffffffffu, v, o);
    return v;
}

__device__ __forceinline__ float rel_bias(const float* __restrict__ bt, int h, int i, int j) {
    int yi = i / 7, xi = i - yi * 7;
    int yj = j / 7, xj = j - yj * 7;
    int idx = (yi - yj + 6) * 13 + (xi - xj + 6);
    return bt[idx * NH + h];
}

__global__ __launch_bounds__(256, 1)
void win_attn_kernel(const float* __restrict__ x,
                     const float* __restrict__ mask,
                     const float* __restrict__ qkv_w,
                     const float* __restrict__ qkv_b,
                     const float* __restrict__ proj_w,
                     const float* __restrict__ proj_b,
                     const float* __restrict__ bt,
                     float* __restrict__ out,
                     int nW)
{
    extern __shared__ float sm[];
    float* osx = sm;                  // x [49][128] then O [49][133]
    float* qs  = osx + OS_SZ;         // Q [49][133]
    float* kts = qs + QS_SZ;          // K^T [128][51]
    float* vs  = kts + KT_SZ;         // V [49][128]
    float* ss  = vs + VS_SZ;          // S/P [2 heads][49][53]
    float* ws  = ss + 2 * SS_SZ;      // weight slab [384][65] (k-slab of 64)

    const int t = threadIdx.x;
    const int w = blockIdx.x;
    const long base = (long)w * (NT * CD);
    const int tn = t & 31, tm = t >> 5;

    // ---- load x ----
    for (int idx = t; idx < NT * CD; idx += 256) osx[idx] = x[base + idx];

    // ---- QKV GEMM: [49 x 384] = x[49x128] @ qkv_w^T ----
    {
        float acc[7][12];
#pragma unroll
        for (int r = 0; r < 7; r++)
#pragma unroll
            for (int c = 0; c < 12; c++) acc[r][c] = 0.f;

        const float4* w4 = reinterpret_cast<const float4*>(qkv_w);
        for (int ks = 0; ks < CD; ks += 64) {
            __syncthreads();
            // stage k-slab transposed-free: ws[col][kk], coalesced global reads
            for (int idx = t; idx < 384 * 16; idx += 256) {
                int col = idx >> 4, q = idx & 15;
                float4 v = w4[col * 32 + (ks >> 2) + q];
                float* p = &ws[col * WS_LD + q * 4];
                p[0] = v.x; p[1] = v.y; p[2] = v.z; p[3] = v.w;
            }
            __syncthreads();
            if (tm < 7) {
#pragma unroll 2
                for (int kk = 0; kk < 64; kk++) {
                    float a[7];
#pragma unroll
                    for (int r = 0; r < 7; r++) a[r] = osx[(tm * 7 + r) * CD + ks + kk];
#pragma unroll
                    for (int c = 0; c < 12; c++) {
                        float b = ws[(tn + 32 * c) * WS_LD + kk];
#pragma unroll
                        for (int r = 0; r < 7; r++) acc[r][c] = fmaf(a[r], b, acc[r][c]);
                    }
                }
            }
        }
        if (tm < 7) {
#pragma unroll
            for (int c = 0; c < 12; c++) {
                int col = tn + 32 * c;
                float bb = qkv_b[col];
#pragma unroll
                for (int r = 0; r < 7; r++) {
                    int row = tm * 7 + r;
                    float v = acc[r][c] + bb;
                    if (c < 4)       qs[row * QS_LD + col] = v;               // Q
                    else if (c < 8)  kts[(col - 128) * KT_LD + row] = v;      // K^T
                    else             vs[row * CD + (col - 256)] = v;          // V
                }
            }
        }
    }
    __syncthreads();

    // ---- attention, two heads at a time ----
    const float scale = 0.1767766952966369f; // 32^-0.5
    const float* mrow = mask + (long)(w % nW) * (NT * NT);

    for (int h0 = 0; h0 < NH; h0 += 2) {
        // S = Q K^T * scale
        {
            int th = t & 127, hh = t >> 7;
            if (th < 100) {
                int ip = th >> 2, jg = th & 3;
                int i0 = ip * 2;
                int h = h0 + hh;
                bool has1 = (i0 + 1) < NT;
                float accs0[13], accs1[13];
#pragma unroll
                for (int jj = 0; jj < 13; jj++) { accs0[jj] = 0.f; accs1[jj] = 0.f; }
                const float* qrow0 = &qs[i0 * QS_LD + h * DH];
                const float* qrow1 = &qs[(i0 + 1) * QS_LD + h * DH];
#pragma unroll 2
                for (int k = 0; k < DH; k++) {
                    float q0 = qrow0[k];
                    float q1 = has1 ? qrow1[k] : 0.f;
                    const float* krow = &kts[(h * DH + k) * KT_LD + jg * 13];
#pragma unroll
                    for (int jj = 0; jj < 13; jj++) {
                        float kv = krow[jj];
                        accs0[jj] = fmaf(q0, kv, accs0[jj]);
                        accs1[jj] = fmaf(q1, kv, accs1[jj]);
                    }
                }
                float* sp = ss + hh * SS_SZ;
#pragma unroll
                for (int jj = 0; jj < 13; jj++) {
                    int j = jg * 13 + jj;
                    if (j < NT) {
                        sp[i0 * SS_LD + j] = accs0[jj] * scale;
                        if (has1) sp[(i0 + 1) * SS_LD + j] = accs1[jj] * scale;
                    }
                }
            }
        }
        __syncthreads();

        // softmax rows (+ rel-pos bias + mask), warp per row
        {
            int wid = t >> 5, l = t & 31;
            int hh = wid >> 2, h = h0 + hh;
            float* sp = ss + hh * SS_SZ;
            for (int p = 0; p < 13; p++) {
                int i = (wid & 3) + 4 * p;
                if (i < NT) {
                    int j2 = l + 32;
                    bool has2 = j2 < NT;
                    float v0 = sp[i * SS_LD + l] + rel_bias(bt, h, i, l) + mrow[i * NT + l];
                    float v1 = has2 ? (sp[i * SS_LD + j2] + rel_bias(bt, h, i, j2) + mrow[i * NT + j2])
                                    : -1e30f;
                    float m = warp_max(fmaxf(v0, v1));
                    float e0 = __expf(v0 - m);
                    float e1 = has2 ? __expf(v1 - m) : 0.f;
                    float s = warp_sum(e0 + e1);
                    float inv = 1.f / s;
                    sp[i * SS_LD + l] = e0 * inv;
                    if (has2) sp[i * SS_LD + j2] = e1 * inv;
                }
            }
        }
        __syncthreads();

        // O = P V  (lanes over rows i, warp covers an 8-wide dh slice)
        {
            int g = t >> 5, l = t & 31;
            int hh = g >> 2, h = h0 + hh;
            int dh0 = (g & 3) * 8;
            const float* sp = ss + hh * SS_SZ;
            bool has2 = (l + 32) < NT;
            float acc0[8], acc1[8];
#pragma unroll
            for (int u = 0; u < 8; u++) { acc0[u] = 0.f; acc1[u] = 0.f; }
            for (int j = 0; j < NT; j++) {
                float p0 = sp[l * SS_LD + j];
                float p1 = has2 ? sp[(l + 32) * SS_LD + j] : 0.f;
                const float* vr = &vs[j * CD + h * DH + dh0];
#pragma unroll
                for (int u = 0; u < 8; u++) {
                    float vv = vr[u];
                    acc0[u] = fmaf(p0, vv, acc0[u]);
                    acc1[u] = fmaf(p1, vv, acc1[u]);
                }
            }
#pragma unroll
            for (int u = 0; u < 8; u++) {
                osx[l * OS_LD + h * DH + dh0 + u] = acc0[u];
                if (has2) osx[(l + 32) * OS_LD + h * DH + dh0 + u] = acc1[u];
            }
        }
        __syncthreads();
    }

    // ---- proj GEMM: out[49x128] = O[49x128] @ proj_w^T + b ----
    {
        float accp[7][4];
#pragma unroll
        for (int r = 0; r < 7; r++)
#pragma unroll
            for (int c = 0; c < 4; c++) accp[r][c] = 0.f;

        const float4* p4 = reinterpret_cast<const float4*>(proj_w);
        for (int ks = 0; ks < CD; ks += 64) {
            __syncthreads();
            for (int idx = t; idx < 128 * 16; idx += 256) {
                int col = idx >> 4, q = idx & 15;
                float4 v = p4[col * 32 + (ks >> 2) + q];
                float* p = &ws[col * WS_LD + q * 4];
                p[0] = v.x; p[1] = v.y; p[2] = v.z; p[3] = v.w;
            }
            __syncthreads();
            if (tm < 7) {
#pragma unroll 2
                for (int kk = 0; kk < 64; kk++) {
                    float a[7];
#pragma unroll
                    for (int r = 0; r < 7; r++) a[r] = osx[(tm * 7 + r) * OS_LD + ks + kk];
#pragma unroll
                    for (int c = 0; c < 4; c++) {
                        float b = ws[(tn + 32 * c) * WS_LD + kk];
#pragma unroll
                        for (int r = 0; r < 7; r++) accp[r][c] = fmaf(a[r], b, accp[r][c]);
                    }
                }
            }
        }
        if (tm < 7) {
#pragma unroll
            for (int c = 0; c < 4; c++) {
                int col = tn + 32 * c;
                float bb = proj_b[col];
#pragma unroll
                for (int r = 0; r < 7; r++) {
                    int row = tm * 7 + r;
                    out[base + row * CD + col] = accp[r][c] + bb;
                }
            }
        }
    }
}

extern "C" void kernel_launch(void* const* d_in, const int* in_sizes, int n_in,
                              void* d_out, int out_size) {
    const float* x      = (const float*)d_in[0];
    const float* mask   = (const float*)d_in[1];
    const float* qkv_w  = (const float*)d_in[2];
    const float* qkv_b  = (const float*)d_in[3];
    const float* proj_w = (const float*)d_in[4];
    const float* proj_b = (const float*)d_in[5];
    const float* bt     = (const float*)d_in[6];
    float* out = (float*)d_out;

    int B  = in_sizes[0] / (NT * CD);     // 16384
    int nW = in_sizes[1] / (NT * NT);     // 1024

    cudaFuncSetAttribute(win_attn_kernel,
                         cudaFuncAttributeMaxDynamicSharedMemorySize, SMEM_BYTES);
    win_attn_kernel<<<B, 256, SMEM_BYTES>>>(x, mask, qkv_w, qkv_b,
                                            proj_w, proj_b, bt, out, nW);
}

// round 4
// speedup vs baseline: 1.0355x; 1.0355x over previous
#include <cuda_runtime.h>
#include <math.h>

#define NT 49
#define CD 128
#define NH 4
#define DH 32

#define OS_LD 133
#define QS_LD 133
#define KT_LD 51
#define SS_LD 53
#define WS_LD 65

#define OS_SZ (NT*OS_LD)          /* x (stride 128) then O (stride 133) */
#define QS_SZ (NT*QS_LD)
#define KT_SZ (CD*KT_LD + 16)
#define VS_SZ (NT*CD)
#define SS_SZ (NT*SS_LD)          /* per head; 4 heads live at once (aliases WS) */
#define WS_SZ (384*WS_LD)         /* weight slab; >= 4*SS_SZ */

#define SMEM_FLOATS (OS_SZ + QS_SZ + KT_SZ + VS_SZ + WS_SZ)
#define SMEM_BYTES (SMEM_FLOATS*4)

__device__ __forceinline__ float warp_max(float v) {
#pragma unroll
    for (int o = 16; o > 0; o >>= 1) v = fmaxf(v, __shfl_xor_sync(0xffffffffu, v, o));
    return v;
}
__device__ __forceinline__ float warp_sum(float v) {
#pragma unroll
    for (int o = 16; o > 0; o >>= 1) v += __shfl_xor_sync(0xffffffffu, v, o);
    return v;
}

__device__ __forceinline__ float rel_bias(const float* __restrict__ bt, int h, int i, int j) {
    int yi = i / 7, xi = i - yi * 7;
    int yj = j / 7, xj = j - yj * 7;
    int idx = (yi - yj + 6) * 13 + (xi - xj + 6);
    return bt[idx * NH + h];
}

__global__ __launch_bounds__(512, 1)
void win_attn_kernel(const float* __restrict__ x,
                     const float* __restrict__ mask,
                     const float* __restrict__ qkv_w,
                     const float* __restrict__ qkv_b,
                     const float* __restrict__ proj_w,
                     const float* __restrict__ proj_b,
                     const float* __restrict__ bt,
                     float* __restrict__ out,
                     int nW)
{
    extern __shared__ float sm[];
    float* osx = sm;                  // x [49][128] then O [49][133]
    float* qs  = osx + OS_SZ;         // Q [49][133]
    float* kts = qs + QS_SZ;          // K^T [128][51]
    float* vs  = kts + KT_SZ;         // V [49][128]
    float* ws  = vs + VS_SZ;          // weight slab [384][65]  (k-slab of 64)
    float* ss  = ws;                  // S/P [4 heads][49][53]   (aliases ws)

    const int t = threadIdx.x;
    const int w = blockIdx.x;
    const long base = (long)w * (NT * CD);
    const int tn = t & 31, tm = t >> 5;   // 16 warps

    // ---- load x ----
    for (int idx = t; idx < NT * CD; idx += 512) osx[idx] = x[base + idx];

    // ---- QKV GEMM: [49 x 384] = x[49x128] @ qkv_w^T ----
    // warps 0..6 -> cols 0..191, warps 8..14 -> cols 192..383, warps 7/15 idle
    {
        float acc[7][6];
#pragma unroll
        for (int r = 0; r < 7; r++)
#pragma unroll
            for (int c = 0; c < 6; c++) acc[r][c] = 0.f;

        const int rw = tm & 7;
        const bool active = rw < 7;
        const int cbase = (tm < 8) ? 0 : 6;

        const float4* w4 = reinterpret_cast<const float4*>(qkv_w);
        for (int ks = 0; ks < CD; ks += 64) {
            __syncthreads();
            for (int idx = t; idx < 384 * 16; idx += 512) {
                int col = idx >> 4, q = idx & 15;
                float4 v = w4[col * 32 + (ks >> 2) + q];
                float* p = &ws[col * WS_LD + q * 4];
                p[0] = v.x; p[1] = v.y; p[2] = v.z; p[3] = v.w;
            }
            __syncthreads();
            if (active) {
#pragma unroll 2
                for (int kk = 0; kk < 64; kk++) {
                    float a[7];
#pragma unroll
                    for (int r = 0; r < 7; r++) a[r] = osx[(rw * 7 + r) * CD + ks + kk];
#pragma unroll
                    for (int c = 0; c < 6; c++) {
                        float b = ws[(tn + 32 * (cbase + c)) * WS_LD + kk];
#pragma unroll
                        for (int r = 0; r < 7; r++) acc[r][c] = fmaf(a[r], b, acc[r][c]);
                    }
                }
            }
        }
        __syncthreads();   // ws dead; ss (same memory) about to be written
        if (active) {
#pragma unroll
            for (int c = 0; c < 6; c++) {
                int col = tn + 32 * (cbase + c);
                float bb = qkv_b[col];
#pragma unroll
                for (int r = 0; r < 7; r++) {
                    int row = rw * 7 + r;
                    float v = acc[r][c] + bb;
                    if (col < 128)       qs[row * QS_LD + col] = v;               // Q
                    else if (col < 256)  kts[(col - 128) * KT_LD + row] = v;      // K^T
                    else                 vs[row * CD + (col - 256)] = v;          // V
                }
            }
        }
    }
    __syncthreads();

    // ---- attention: all 4 heads at once ----
    const float scale = 0.1767766952966369f; // 32^-0.5
    const float* mrow = mask + (long)(w % nW) * (NT * NT);

    // S = Q K^T * scale   (128 threads per head)
    {
        int th = t & 127, h = t >> 7;           // h = 0..3
        if (th < 100) {
            int ip = th >> 2, jg = th & 3;
            int i0 = ip * 2;
            bool has1 = (i0 + 1) < NT;
            float accs0[13], accs1[13];
#pragma unroll
            for (int jj = 0; jj < 13; jj++) { accs0[jj] = 0.f; accs1[jj] = 0.f; }
            const float* qrow0 = &qs[i0 * QS_LD + h * DH];
            const float* qrow1 = &qs[(i0 + 1) * QS_LD + h * DH];
#pragma unroll 2
            for (int k = 0; k < DH; k++) {
                float q0 = qrow0[k];
                float q1 = has1 ? qrow1[k] : 0.f;
                const float* krow = &kts[(h * DH + k) * KT_LD + jg * 13];
#pragma unroll
                for (int jj = 0; jj < 13; jj++) {
                    float kv = krow[jj];
                    accs0[jj] = fmaf(q0, kv, accs0[jj]);
                    accs1[jj] = fmaf(q1, kv, accs1[jj]);
                }
            }
            float* sp = ss + h * SS_SZ;
#pragma unroll
            for (int jj = 0; jj < 13; jj++) {
                int j = jg * 13 + jj;
                if (j < NT) {
                    sp[i0 * SS_LD + j] = accs0[jj] * scale;
                    if (has1) sp[(i0 + 1) * SS_LD + j] = accs1[jj] * scale;
                }
            }
        }
    }
    __syncthreads();

    // softmax rows (+ rel-pos bias + mask), warp per row, 4 warps per head
    {
        int wid = tm, l = tn;
        int h = wid >> 2;
        float* sp = ss + h * SS_SZ;
        for (int p = 0; p < 13; p++) {
            int i = (wid & 3) + 4 * p;
            if (i < NT) {
                int j2 = l + 32;
                bool has2 = j2 < NT;
                float v0 = sp[i * SS_LD + l] + rel_bias(bt, h, i, l) + mrow[i * NT + l];
                float v1 = has2 ? (sp[i * SS_LD + j2] + rel_bias(bt, h, i, j2) + mrow[i * NT + j2])
                                : -1e30f;
                float m = warp_max(fmaxf(v0, v1));
                float e0 = __expf(v0 - m);
                float e1 = has2 ? __expf(v1 - m) : 0.f;
                float s = warp_sum(e0 + e1);
                float inv = 1.f / s;
                sp[i * SS_LD + l] = e0 * inv;
                if (has2) sp[i * SS_LD + j2] = e1 * inv;
            }
        }
    }
    __syncthreads();

    // O = P V  (4 warps per head, each warp covers an 8-wide dh slice)
    {
        int g = tm, l = tn;
        int h = g >> 2;
        int dh0 = (g & 3) * 8;
        const float* sp = ss + h * SS_SZ;
        bool has2 = (l + 32) < NT;
        float acc0[8], acc1[8];
#pragma unroll
        for (int u = 0; u < 8; u++) { acc0[u] = 0.f; acc1[u] = 0.f; }
        for (int j = 0; j < NT; j++) {
            float p0 = sp[l * SS_LD + j];
            float p1 = has2 ? sp[(l + 32) * SS_LD + j] : 0.f;
            const float* vr = &vs[j * CD + h * DH + dh0];
#pragma unroll
            for (int u = 0; u < 8; u++) {
                float vv = vr[u];
                acc0[u] = fmaf(p0, vv, acc0[u]);
                acc1[u] = fmaf(p1, vv, acc1[u]);
            }
        }
#pragma unroll
        for (int u = 0; u < 8; u++) {
            osx[l * OS_LD + h * DH + dh0 + u] = acc0[u];
            if (has2) osx[(l + 32) * OS_LD + h * DH + dh0 + u] = acc1[u];
        }
    }
    __syncthreads();

    // ---- proj GEMM: out[49x128] = O[49x128] @ proj_w^T + b ----
    // warps 0..6 -> cols 0..63, warps 8..14 -> cols 64..127
    {
        float accp[7][2];
#pragma unroll
        for (int r = 0; r < 7; r++)
#pragma unroll
            for (int c = 0; c < 2; c++) accp[r][c] = 0.f;

        const int rw = tm & 7;
        const bool active = rw < 7;
        const int cbase = (tm < 8) ? 0 : 2;

        const float4* p4 = reinterpret_cast<const float4*>(proj_w);
        for (int ks = 0; ks < CD; ks += 64) {
            __syncthreads();
            for (int idx = t; idx < 128 * 16; idx += 512) {
                int col = idx >> 4, q = idx & 15;
                float4 v = p4[col * 32 + (ks >> 2) + q];
                float* p = &ws[col * WS_LD + q * 4];
                p[0] = v.x; p[1] = v.y; p[2] = v.z; p[3] = v.w;
            }
            __syncthreads();
            if (active) {
#pragma unroll 2
                for (int kk = 0; kk < 64; kk++) {
                    float a[7];
#pragma unroll
                    for (int r = 0; r < 7; r++) a[r] = osx[(rw * 7 + r) * OS_LD + ks + kk];
#pragma unroll
                    for (int c = 0; c < 2; c++) {
                        float b = ws[(tn + 32 * (cbase + c)) * WS_LD + kk];
#pragma unroll
                        for (int r = 0; r < 7; r++) accp[r][c] = fmaf(a[r], b, accp[r][c]);
                    }
                }
            }
        }
        if (active) {
#pragma unroll
            for (int c = 0; c < 2; c++) {
                int col = tn + 32 * (cbase + c);
                float bb = proj_b[col];
#pragma unroll
                for (int r = 0; r < 7; r++) {
                    int row = rw * 7 + r;
                    out[base + row * CD + col] = accp[r][c] + bb;
                }
            }
        }
    }
}

extern "C" void kernel_launch(void* const* d_in, const int* in_sizes, int n_in,
                              void* d_out, int out_size) {
    const float* x      = (const float*)d_in[0];
    const float* mask   = (const float*)d_in[1];
    const float* qkv_w  = (const float*)d_in[2];
    const float* qkv_b  = (const float*)d_in[3];
    const float* proj_w = (const float*)d_in[4];
    const float* proj_b = (const float*)d_in[5];
    const float* bt     = (const float*)d_in[6];
    float* out = (float*)d_out;

    int B  = in_sizes[0] / (NT * CD);     // 16384
    int nW = in_sizes[1] / (NT * NT);     // 1024

    cudaFuncSetAttribute(win_attn_kernel,
                         cudaFuncAttributeMaxDynamicSharedMemorySize, SMEM_BYTES);
    win_attn_kernel<<<B, 512, SMEM_BYTES>>>(x, mask, qkv_w, qkv_b,
                                            proj_w, proj_b, bt, out, nW);
}

// round 6
// speedup vs baseline: 1.6203x; 1.5647x over previous
#include <cuda_runtime.h>
#include <cuda_bf16.h>
#include <cstdint>

#define NT 49
#define CD 128

/* float-index smem offsets */
#define FA   0            /* A bf16 [2][64][128] = 32768B = 8192 fl */
#define FB   8192         /* B region 98304B = 24576 fl (qkv slab / S / proj B) */
#define FQ   32768        /* QKV region */
#define F_Q  (FQ)                 /* Q  [49][133] */
#define F_KT (FQ + 6517)          /* KT [128][51] */
#define F_V  (FQ + 13045)         /* V  [49][129] */
#define F_QB (FQ + 19366)         /* qkv_b 384 */
#define F_PB (FQ + 19750)         /* proj_b 128 */
#define SMEM_BYTES 210688

#define QS_LD 133
#define KT_LD 51
#define VS_LD 129
#define SS_LD 53
#define SS_SZ (NT*SS_LD)
#define BO_LD 132

__device__ __align__(16) uint16_t g_qkvw[98304];  /* [slab2][split2][384][64] swizzled bf16 */
__device__ __align__(16) uint16_t g_projw[32768]; /* [split2][128][128] swizzled bf16 */

__device__ __forceinline__ uint32_t smem_u32(const void* p) {
    uint32_t a;
    asm("{ .reg .u64 t; cvta.to.shared.u64 t, %1; cvt.u32.u64 %0, t; }" : "=r"(a) : "l"(p));
    return a;
}
__device__ __forceinline__ void ldsm4(uint32_t* r, uint32_t a) {
    asm volatile("ldmatrix.sync.aligned.m8n8.x4.shared.b16 {%0,%1,%2,%3}, [%4];"
        : "=r"(r[0]), "=r"(r[1]), "=r"(r[2]), "=r"(r[3]) : "r"(a));
}
__device__ __forceinline__ void mma_bf16(float* d, const uint32_t* a, const uint32_t* b) {
    asm volatile("mma.sync.aligned.m16n8k16.row.col.f32.bf16.bf16.f32 "
        "{%0,%1,%2,%3}, {%4,%5,%6,%7}, {%8,%9}, {%0,%1,%2,%3};"
        : "+f"(d[0]), "+f"(d[1]), "+f"(d[2]), "+f"(d[3])
        : "r"(a[0]), "r"(a[1]), "r"(a[2]), "r"(a[3]), "r"(b[0]), "r"(b[1]));
}

__device__ __forceinline__ float warp_max(float v) {
#pragma unroll
    for (int o = 16; o > 0; o >>= 1) v = fmaxf(v, __shfl_xor_sync(0xffffffffu, v, o));
    return v;
}
__device__ __forceinline__ float warp_sum(float v) {
#pragma unroll
    for (int o = 16; o > 0; o >>= 1) v += __shfl_xor_sync(0xffffffffu, v, o);
    return v;
}
__device__ __forceinline__ float rel_bias(const float* __restrict__ bt, int h, int i, int j) {
    int yi = i / 7, xi = i - yi * 7;
    int yj = j / 7, xj = j - yj * 7;
    return bt[((yi - yj + 6) * 13 + (xi - xj + 6)) * 4 + h];
}

/* ---- prologue: split weights into bf16 hi/lo swizzled smem-images ---- */
__global__ void prep_w(const float* __restrict__ qkv_w, const float* __restrict__ proj_w) {
    int i = blockIdx.x * blockDim.x + threadIdx.x;
    if (i < 384 * 128) {
        int n = i >> 7, k = i & 127;
        float f = qkv_w[i];
        __nv_bfloat16 h = __float2bfloat16_rn(f);
        __nv_bfloat16 l = __float2bfloat16_rn(f - __bfloat162float(h));
        int s = k >> 6, ko = k & 63;
        int sw = (((ko >> 3) ^ (n & 7)) << 3) + (k & 7);
        g_qkvw[((s * 2 + 0) * 384 + n) * 64 + sw] = __bfloat16_as_ushort(h);
        g_qkvw[((s * 2 + 1) * 384 + n) * 64 + sw] = __bfloat16_as_ushort(l);
    }
    if (i < 128 * 128) {
        int n = i >> 7, k = i & 127;
        float f = proj_w[i];
        __nv_bfloat16 h = __float2bfloat16_rn(f);
        __nv_bfloat16 l = __float2bfloat16_rn(f - __bfloat162float(h));
        int sw = (((k >> 3) ^ (n & 7)) << 3) + (k & 7);
        g_projw[(0 * 128 + n) * 128 + sw] = __bfloat16_as_ushort(h);
        g_projw[(1 * 128 + n) * 128 + sw] = __bfloat16_as_ushort(l);
    }
}

/* ---- main fused kernel ---- */
__global__ __launch_bounds__(512, 1)
void win_attn_mma(const float* __restrict__ x,
                  const float* __restrict__ mask,
                  const float* __restrict__ qkv_b,
                  const float* __restrict__ proj_b,
                  const float* __restrict__ bt,
                  float* __restrict__ out,
                  int nW)
{
    extern __shared__ float sm[];
    uint16_t* abuf = (uint16_t*)sm;
    const int t = threadIdx.x;
    const int w = blockIdx.x;
    const long base = (long)w * (NT * CD);
    const int tn = t & 31, tm = t >> 5;
    const uint32_t smb = smem_u32(sm);

    /* ---- stage x -> A hi/lo (swizzled bf16); zero pad rows; biases ---- */
    for (int idx = t; idx < NT * CD; idx += 512) {
        int r = idx >> 7, k = idx & 127;
        float f = x[base + idx];
        __nv_bfloat16 h = __float2bfloat16_rn(f);
        __nv_bfloat16 l = __float2bfloat16_rn(f - __bfloat162float(h));
        int sw = ((k >> 3) ^ (r & 7)) * 8 + (k & 7);
        abuf[r * 128 + sw]        = __bfloat16_as_ushort(h);
        abuf[(64 + r) * 128 + sw] = __bfloat16_as_ushort(l);
    }
    for (int idx = t; idx < 15 * CD; idx += 512) {
        int r = 49 + (idx >> 7), k = idx & 127;
        int sw = ((k >> 3) ^ (r & 7)) * 8 + (k & 7);
        abuf[r * 128 + sw] = 0;
        abuf[(64 + r) * 128 + sw] = 0;
    }
    if (t < 384) sm[F_QB + t] = qkv_b[t];
    if (t < 128) sm[F_PB + t] = proj_b[t];
    __syncthreads();

    const int l = tn;
    const int wm = tm & 1, wn = tm >> 1;
    const int a_r_off = (l & 7) + ((l >> 3) & 1) * 8;
    const int a_c_off = l >> 4;
    const int b_n_off = (l & 7) + (l >> 4) * 8;
    const int b_c_off = (l >> 3) & 1;

    /* ======== QKV GEMM: D[64x384] = A[64x128] @ W^T, split-bf16 ======== */
    float dacc[2][6][4];
#pragma unroll
    for (int a = 0; a < 2; a++)
#pragma unroll
        for (int b = 0; b < 6; b++)
#pragma unroll
            for (int c = 0; c < 4; c++) dacc[a][b][c] = 0.f;

    for (int s = 0; s < 2; s++) {
        {   /* stage B k-slab [2][384][64] bf16 = 6144 float4 */
            const float4* src = ((const float4*)g_qkvw) + s * 6144;
            float4* dst = (float4*)(sm + FB);
            for (int i = t; i < 6144; i += 512) dst[i] = src[i];
        }
        __syncthreads();
#pragma unroll
        for (int kk = 0; kk < 4; kk++) {
            uint32_t af[2][2][4];
#pragma unroll
            for (int mt = 0; mt < 2; mt++)
#pragma unroll
                for (int sp = 0; sp < 2; sp++) {
                    int r = wm * 32 + mt * 16 + a_r_off;
                    int ch = s * 8 + kk * 2 + a_c_off;
                    uint32_t ad = smb + ((((sp * 64 + r) * 128) + ((ch ^ (r & 7)) << 3)) << 1);
                    ldsm4(af[mt][sp], ad);
                }
            uint32_t bf[6][2][2];
#pragma unroll
            for (int np = 0; np < 3; np++)
#pragma unroll
                for (int sp = 0; sp < 2; sp++) {
                    int n = wn * 48 + np * 16 + b_n_off;
                    int ch = kk * 2 + b_c_off;
                    uint32_t ad = smb + FB * 4 + ((((sp * 384 + n) * 64) + ((ch ^ (n & 7)) << 3)) << 1);
                    uint32_t r4[4]; ldsm4(r4, ad);
                    bf[np * 2][sp][0] = r4[0]; bf[np * 2][sp][1] = r4[1];
                    bf[np * 2 + 1][sp][0] = r4[2]; bf[np * 2 + 1][sp][1] = r4[3];
                }
#pragma unroll
            for (int mt = 0; mt < 2; mt++)
#pragma unroll
                for (int nt = 0; nt < 6; nt++) {
                    mma_bf16(dacc[mt][nt], af[mt][0], bf[nt][0]);  /* hi*hi */
                    mma_bf16(dacc[mt][nt], af[mt][0], bf[nt][1]);  /* hi*lo */
                    mma_bf16(dacc[mt][nt], af[mt][1], bf[nt][0]);  /* lo*hi */
                }
        }
        __syncthreads();
    }

    /* ---- epilogue: accum -> Q / K^T / V (+bias) ---- */
    {
        int r0 = wm * 32 + (l >> 2);
        int c00 = wn * 48 + (l & 3) * 2;
#pragma unroll
        for (int mt = 0; mt < 2; mt++)
#pragma unroll
            for (int nt = 0; nt < 6; nt++)
#pragma unroll
                for (int rg = 0; rg < 4; rg++) {
                    int row = r0 + mt * 16 + ((rg >> 1) << 3);
                    int col = c00 + nt * 8 + (rg & 1);
                    if (row < NT) {
                        float v = dacc[mt][nt][rg] + sm[F_QB + col];
                        if (col < 128)      sm[F_Q + row * QS_LD + col] = v;
                        else if (col < 256) sm[F_KT + (col - 128) * KT_LD + row] = v;
                        else                sm[F_V + row * VS_LD + (col - 256)] = v;
                    }
                }
    }
    __syncthreads();

    /* ======== attention (FFMA), 4 heads; S in B region ======== */
    const float scale = 0.1767766952966369f;
    const float* mrow = mask + (long)(w % nW) * (NT * NT);
    float* qs  = sm + F_Q;
    float* kts = sm + F_KT;
    float* vs  = sm + F_V;
    float* ss  = sm + FB;

    {   /* S = Q K^T * scale */
        int th = t & 127, h = t >> 7;
        if (th < 100) {
            int ip = th >> 2, jg = th & 3;
            int i0 = ip * 2;
            bool has1 = (i0 + 1) < NT;
            float a0[13], a1[13];
#pragma unroll
            for (int jj = 0; jj < 13; jj++) { a0[jj] = 0.f; a1[jj] = 0.f; }
            const float* q0p = &qs[i0 * QS_LD + h * 32];
            const float* q1p = &qs[(i0 + 1) * QS_LD + h * 32];
#pragma unroll 2
            for (int k = 0; k < 32; k++) {
                float q0 = q0p[k];
                float q1 = has1 ? q1p[k] : 0.f;
                const float* kr = &kts[(h * 32 + k) * KT_LD + jg * 13];
#pragma unroll
                for (int jj = 0; jj < 13; jj++) {
                    float kv = kr[jj];
                    a0[jj] = fmaf(q0, kv, a0[jj]);
                    a1[jj] = fmaf(q1, kv, a1[jj]);
                }
            }
            float* sp = ss + h * SS_SZ;
#pragma unroll
            for (int jj = 0; jj < 13; jj++) {
                int j = jg * 13 + jj;
                if (j < NT) {
                    sp[i0 * SS_LD + j] = a0[jj] * scale;
                    if (has1) sp[(i0 + 1) * SS_LD + j] = a1[jj] * scale;
                }
            }
        }
    }
    __syncthreads();

    {   /* softmax + rel-pos bias + mask */
        int wid = tm, ln = tn;
        int h = wid >> 2;
        float* sp = ss + h * SS_SZ;
        for (int p = 0; p < 13; p++) {
            int i = (wid & 3) + 4 * p;
            if (i < NT) {
                int j2 = ln + 32;
                bool has2 = j2 < NT;
                float v0 = sp[i * SS_LD + ln] + rel_bias(bt, h, i, ln) + mrow[i * NT + ln];
                float v1 = has2 ? (sp[i * SS_LD + j2] + rel_bias(bt, h, i, j2) + mrow[i * NT + j2])
                                : -1e30f;
                float m = warp_max(fmaxf(v0, v1));
                float e0 = __expf(v0 - m);
                float e1 = has2 ? __expf(v1 - m) : 0.f;
                float sum = warp_sum(e0 + e1);
                float inv = 1.f / sum;
                sp[i * SS_LD + ln] = e0 * inv;
                if (has2) sp[i * SS_LD + j2] = e1 * inv;
            }
        }
    }
    __syncthreads();

    {   /* O = P V -> A region as split-bf16 (packed 16B stores) */
        int g = tm, lq = tn;
        int h = g >> 2;
        int dh0 = (g & 3) * 8;
        const float* sp = ss + h * SS_SZ;
        bool has2 = (lq + 32) < NT;
        float c0[8], c1[8];
#pragma unroll
        for (int u = 0; u < 8; u++) { c0[u] = 0.f; c1[u] = 0.f; }
        for (int j = 0; j < NT; j++) {
            float p0 = sp[lq * SS_LD + j];
            float p1 = has2 ? sp[(lq + 32) * SS_LD + j] : 0.f;
            const float* vr = &vs[j * VS_LD + h * 32 + dh0];
#pragma unroll
            for (int u = 0; u < 8; u++) {
                float vv = vr[u];
                c0[u] = fmaf(p0, vv, c0[u]);
                c1[u] = fmaf(p1, vv, c1[u]);
            }
        }
        int ch = (h * 32 + dh0) >> 3;
#pragma unroll
        for (int pass = 0; pass < 2; pass++) {
            int row = pass ? (lq + 32) : lq;
            const float* v = pass ? c1 : c0;
            if (pass && !has2) break;
            uint32_t hi[4], lo[4];
#pragma unroll
            for (int j2 = 0; j2 < 4; j2++) {
                float f0 = v[2 * j2], f1 = v[2 * j2 + 1];
                __nv_bfloat16 h0 = __float2bfloat16_rn(f0);
                __nv_bfloat16 h1 = __float2bfloat16_rn(f1);
                __nv_bfloat16 l0 = __float2bfloat16_rn(f0 - __bfloat162float(h0));
                __nv_bfloat16 l1 = __float2bfloat16_rn(f1 - __bfloat162float(h1));
                hi[j2] = (uint32_t)__bfloat16_as_ushort(h0) | ((uint32_t)__bfloat16_as_ushort(h1) << 16);
                lo[j2] = (uint32_t)__bfloat16_as_ushort(l0) | ((uint32_t)__bfloat16_as_ushort(l1) << 16);
            }
            int sw = (ch ^ (row & 7)) << 3;
            *(uint4*)&abuf[row * 128 + sw]        = make_uint4(hi[0], hi[1], hi[2], hi[3]);
            *(uint4*)&abuf[(64 + row) * 128 + sw] = make_uint4(lo[0], lo[1], lo[2], lo[3]);
        }
    }
    __syncthreads();

    /* ======== proj GEMM: D[64x128] = O @ proj_w^T, split-bf16 ======== */
    {   /* stage full proj B [2][128][128] bf16 = 4096 float4 (overwrites S) */
        const float4* src = (const float4*)g_projw;
        float4* dst = (float4*)(sm + FB);
        for (int i = t; i < 4096; i += 512) dst[i] = src[i];
    }
    __syncthreads();

    float pacc[2][2][4];
#pragma unroll
    for (int a = 0; a < 2; a++)
#pragma unroll
        for (int b = 0; b < 2; b++)
#pragma unroll
            for (int c = 0; c < 4; c++) pacc[a][b][c] = 0.f;

#pragma unroll
    for (int kk = 0; kk < 8; kk++) {
        uint32_t af[2][2][4];
#pragma unroll
        for (int mt = 0; mt < 2; mt++)
#pragma unroll
            for (int sp = 0; sp < 2; sp++) {
                int r = wm * 32 + mt * 16 + a_r_off;
                int ch = kk * 2 + a_c_off;
                uint32_t ad = smb + ((((sp * 64 + r) * 128) + ((ch ^ (r & 7)) << 3)) << 1);
                ldsm4(af[mt][sp], ad);
            }
        uint32_t bf2[2][2][2];
#pragma unroll
        for (int sp = 0; sp < 2; sp++) {
            int n = wn * 16 + b_n_off;
            int ch = kk * 2 + b_c_off;
            uint32_t ad = smb + FB * 4 + ((((sp * 128 + n) * 128) + ((ch ^ (n & 7)) << 3)) << 1);
            uint32_t r4[4]; ldsm4(r4, ad);
            bf2[0][sp][0] = r4[0]; bf2[0][sp][1] = r4[1];
            bf2[1][sp][0] = r4[2]; bf2[1][sp][1] = r4[3];
        }
#pragma unroll
        for (int mt = 0; mt < 2; mt++)
#pragma unroll
            for (int nt = 0; nt < 2; nt++) {
                mma_bf16(pacc[mt][nt], af[mt][0], bf2[nt][0]);
                mma_bf16(pacc[mt][nt], af[mt][0], bf2[nt][1]);
                mma_bf16(pacc[mt][nt], af[mt][1], bf2[nt][0]);
            }
    }
    __syncthreads();

    /* ---- proj epilogue: accum+bias -> bounce smem -> coalesced store ---- */
    {
        int r0 = wm * 32 + (l >> 2);
        int c00 = wn * 16 + (l & 3) * 2;
#pragma unroll
        for (int mt = 0; mt < 2; mt++)
#pragma unroll
            for (int nt = 0; nt < 2; nt++)
#pragma unroll
                for (int rg = 0; rg < 4; rg++) {
                    int row = r0 + mt * 16 + ((rg >> 1) << 3);
                    int col = c00 + nt * 8 + (rg & 1);
                    if (row < NT)
                        sm[F_Q + row * BO_LD + col] = pacc[mt][nt][rg] + sm[F_PB + col];
                }
    }
    __syncthreads();
    for (int idx = t; idx < NT * CD; idx += 512)
        out[base + idx] = sm[F_Q + (idx >> 7) * BO_LD + (idx & 127)];
}

extern "C" void kernel_launch(void* const* d_in, const int* in_sizes, int n_in,
                              void* d_out, int out_size) {
    const float* x      = (const float*)d_in[0];
    const float* mask   = (const float*)d_in[1];
    const float* qkv_w  = (const float*)d_in[2];
    const float* qkv_b  = (const float*)d_in[3];
    const float* proj_w = (const float*)d_in[4];
    const float* proj_b = (const float*)d_in[5];
    const float* bt     = (const float*)d_in[6];
    float* out = (float*)d_out;

    int B  = in_sizes[0] / (NT * CD);     /* 16384 */
    int nW = in_sizes[1] / (NT * NT);     /* 1024 */

    prep_w<<<96, 512>>>(qkv_w, proj_w);

    cudaFuncSetAttribute(win_attn_mma,
                         cudaFuncAttributeMaxDynamicSharedMemorySize, SMEM_BYTES);
    win_attn_mma<<<B, 512, SMEM_BYTES>>>(x, mask, qkv_b, proj_b, bt, out, nW);
}